// round 15
// baseline (speedup 1.0000x reference)
#include <cuda_runtime.h>
#include <cuda_bf16.h>
#include <cstdint>
#include <cstddef>

#define H 1024
#define V 32000
#define L 64
#define NEC 3
#define TPB 512
#define NWARP 16
#define EOS_TOK 1
#define DBLK 76            // decode participant blocks

#define TILE_STRIDE 1025
#define SMEM_FLOATS (32 * TILE_STRIDE + 64)

// decode-area smem offsets (in floats)
#define OFF_E    0
#define OFF_H    1024
#define OFF_X    4096
#define OFF_H2   5120
#define OFF_AW   6144
#define OFF_SRED 6208
#define OFF_KRED 6464   /* ull[128] -> 256 floats */
#define OFF_ST   6976   /* int[2]: tok, done */
#define OFF_BMAX 6981
#define OFF_HN   6982
#define OFF_BMN  6983
#define OFF_CCNT 6984   /* int */
#define OFF_CAND 6992   /* int[512] */
#define OFF_LSEH 7600   /* float[64] lse history */

#define EFAC 0.004f

#define OUT_ATT  (L * V)
#define OUT_TOK  (L * V + L * L)

// ------------------------- device scratch (static; no allocs) -------------------------
__device__ float g_gi[(size_t)NEC * 3 * H * L];
__device__ float g_hist[(size_t)NEC * L * H];
__device__ float g_eo[L * H];
__device__ float g_M[H * L];                      // [j][l]
__device__ float g_eh[2][NEC * H];
__device__ float g_part[H * 8];                   // [i]: 0..2 ih, 3..5 hh
__device__ float g_s[L];
__device__ float g_c1[H];
__device__ float g_x[H];
__device__ float g_wn[V];                         // fp32 row norms of W_out
__device__ __nv_bfloat16 g_Wbf[(size_t)V * H];    // bf16 copy of W_out
__device__ unsigned long long g_keys[256];
__device__ float g_sums[256];

// tree barrier state — FENCE-FREE protocol (no __threadfence -> no L1D flush)
__device__ unsigned g_arrL[8 * 64];
__device__ unsigned g_arrM = 0;
__device__ unsigned g_release = 0;
__device__ unsigned g_garr[3 * 64];
__device__ unsigned g_grel[3 * 64];

// ------------------------- helpers -------------------------
__device__ __forceinline__ unsigned ldacq(const unsigned* p) {
    unsigned v;
    asm volatile("ld.acquire.gpu.global.u32 %0, [%1];" : "=r"(v) : "l"(p) : "memory");
    return v;
}
__device__ __forceinline__ void strel(unsigned* p, unsigned v) {
    asm volatile("st.release.gpu.global.u32 [%0], %1;" :: "l"(p), "r"(v) : "memory");
}
__device__ __forceinline__ void strelax(unsigned* p, unsigned v) {
    asm volatile("st.relaxed.gpu.global.u32 [%0], %1;" :: "l"(p), "r"(v) : "memory");
}
__device__ __forceinline__ unsigned atom_add_acqrel(unsigned* p, unsigned v) {
    unsigned r;
    asm volatile("atom.acq_rel.gpu.global.add.u32 %0, [%1], %2;"
                 : "=r"(r) : "l"(p), "r"(v) : "memory");
    return r;
}

__device__ __forceinline__ float wredsum(float v) {
#pragma unroll
    for (int o = 16; o; o >>= 1) v += __shfl_down_sync(0xffffffffu, v, o);
    return v;
}

__device__ __forceinline__ unsigned long long packkey(float v, int r) {
    unsigned u = __float_as_uint(v);
    u = (u & 0x80000000u) ? ~u : (u | 0x80000000u);
    return ((unsigned long long)u << 32) | (unsigned)(~(unsigned)r);
}

__device__ __forceinline__ float sigm(float x) { return 1.f / (1.f + expf(-x)); }

__device__ __forceinline__ float2 bf2f(unsigned u) {
    __nv_bfloat162 t = *reinterpret_cast<__nv_bfloat162*>(&u);
    return __bfloat1622float2(t);
}

// two-level grid barrier (8 leaves), fence-free; works for any contiguous 0..nb-1
__device__ __forceinline__ void gbar(unsigned& gen, int nb, int bid) {
    __syncthreads();
    if (threadIdx.x == 0) {
        const int leaf = bid & 7;
        const unsigned lcnt = (unsigned)((nb - leaf + 7) >> 3);
        unsigned t = atom_add_acqrel(&g_arrL[leaf * 64], 1u);
        if (t == lcnt - 1u) {
            strelax(&g_arrL[leaf * 64], 0u);
            unsigned m = atom_add_acqrel(&g_arrM, 1u);
            if (m == 7u) {
                strelax(&g_arrM, 0u);
                strel(&g_release, gen + 1u);
            } else {
                while (ldacq(&g_release) == gen) { }
            }
        } else {
            while (ldacq(&g_release) == gen) { }
        }
    }
    gen++;
    __syncthreads();
}

// group barrier for one encoder's block set (fence-free)
__device__ __forceinline__ void gbar_grp(unsigned& gen, int e, unsigned cnt) {
    __syncthreads();
    if (threadIdx.x == 0) {
        unsigned t = atom_add_acqrel(&g_garr[e * 64], 1u);
        if (t == cnt - 1u) {
            strelax(&g_garr[e * 64], 0u);
            strel(&g_grel[e * 64], gen + 1u);
        } else {
            while (ldacq(&g_grel[e * 64]) == gen) { }
        }
    }
    gen++;
    __syncthreads();
}

// ------------------------- kernel -------------------------
__global__ void __launch_bounds__(TPB, 1)
ms2s_kernel(const int* __restrict__ q_ids,
            const int* __restrict__ cand_ids,
            const float* __restrict__ enc_emb,
            const float* __restrict__ enc_W_ih,
            const float* __restrict__ enc_W_hh,
            const float* __restrict__ enc_b_ih,
            const float* __restrict__ enc_b_hh,
            const float* __restrict__ dec_emb,
            const float* __restrict__ W_attn,
            const float* __restrict__ b_attn,
            const float* __restrict__ W_comb,
            const float* __restrict__ b_comb,
            const float* __restrict__ dec_W_ih,
            const float* __restrict__ dec_W_hh,
            const float* __restrict__ dec_b_ih,
            const float* __restrict__ dec_b_hh,
            const float* __restrict__ W_out,
            const float* __restrict__ b_out,
            float* __restrict__ out,
            int nblk)
{
    extern __shared__ float sm[];
    const int tid  = threadIdx.x;
    const int warp = tid >> 5;
    const int lane = tid & 31;
    const int bid  = blockIdx.x;
    const int gw   = bid * NWARP + warp;
    const int TW   = nblk * NWARP;
    int* st_i = (int*)(sm + OFF_ST);

    const int dblk = nblk > DBLK ? DBLK : nblk;

    unsigned gen = ldacq(&g_release);

    // =====================================================================
    // Setup: zero enc hidden; bf16 W_out; row norms; gi = W_ih@x + b_ih
    // =====================================================================
    for (int i = bid * TPB + tid; i < NEC * H; i += nblk * TPB) g_eh[0][i] = 0.f;

    {
        const size_t total8 = (size_t)V * H / 8;
        for (size_t u = (size_t)bid * TPB + tid; u < total8; u += (size_t)nblk * TPB) {
            const float4* src = (const float4*)(W_out + u * 8);
            float4 a = __ldg(src), b = __ldg(src + 1);
            unsigned short s0 = __bfloat16_as_ushort(__float2bfloat16_rn(a.x));
            unsigned short s1 = __bfloat16_as_ushort(__float2bfloat16_rn(a.y));
            unsigned short s2 = __bfloat16_as_ushort(__float2bfloat16_rn(a.z));
            unsigned short s3 = __bfloat16_as_ushort(__float2bfloat16_rn(a.w));
            unsigned short s4 = __bfloat16_as_ushort(__float2bfloat16_rn(b.x));
            unsigned short s5 = __bfloat16_as_ushort(__float2bfloat16_rn(b.y));
            unsigned short s6 = __bfloat16_as_ushort(__float2bfloat16_rn(b.z));
            unsigned short s7 = __bfloat16_as_ushort(__float2bfloat16_rn(b.w));
            uint4 o;
            o.x = (unsigned)s0 | ((unsigned)s1 << 16);
            o.y = (unsigned)s2 | ((unsigned)s3 << 16);
            o.z = (unsigned)s4 | ((unsigned)s5 << 16);
            o.w = (unsigned)s6 | ((unsigned)s7 << 16);
            ((uint4*)g_Wbf)[u] = o;
        }
    }
    // row norms of W_out (one warp per row)
    for (int r = gw; r < V; r += TW) {
        const float4* w4 = (const float4*)(W_out + (size_t)r * H);
        float ss = 0.f;
#pragma unroll 2
        for (int k4 = lane; k4 < H / 4; k4 += 32) {
            float4 w = __ldg(&w4[k4]);
            ss += w.x*w.x + w.y*w.y + w.z*w.z + w.w*w.w;
        }
        ss = wredsum(ss);
        if (lane == 0) g_wn[r] = sqrtf(ss);
    }

    {
        const int be   = bid % 3;
        const int rank = bid / 3;
        const int cnt  = (nblk - be + 2) / 3;
        const int rpb  = (3 * H + cnt - 1) / cnt;
        const int r0   = rank * rpb;
        const int r1   = min(3 * H, r0 + rpb);
        int* ids_s = (int*)(sm + 32 * TILE_STRIDE);
        const float* Wih = enc_W_ih + (size_t)be * 3 * H * H;
        const float* emb = enc_emb + (size_t)be * V * H;

        for (int p = 0; p < 2; p++) {
            __syncthreads();
            if (tid < 32) {
                int tIdx = p * 32 + tid;
                ids_s[tid] = (be == 0) ? q_ids[tIdx] : cand_ids[(be - 1) * L + tIdx];
            }
            __syncthreads();
            for (int idx = tid; idx < 32 * H; idx += TPB) {
                int tt = idx >> 10, k = idx & (H - 1);
                sm[tt * TILE_STRIDE + k] = __ldg(&emb[(size_t)ids_s[tt] * H + k]);
            }
            __syncthreads();
            for (int r = r0 + warp; r < r1; r += NWARP) {
                const float4* w4 = (const float4*)(Wih + (size_t)r * H);
                const float* xs = sm + lane * TILE_STRIDE;
                float acc = 0.f;
#pragma unroll 4
                for (int k4 = 0; k4 < H / 4; k4++) {
                    float4 w = __ldg(&w4[k4]);
                    int k = k4 * 4;
                    acc += w.x * xs[k] + w.y * xs[k + 1] + w.z * xs[k + 2] + w.w * xs[k + 3];
                }
                g_gi[((size_t)be * 3 * H + r) * L + p * 32 + lane] =
                    acc + __ldg(&enc_b_ih[be * 3 * H + r]);
            }
        }
    }
    gbar(gen, nblk, bid);

    // =====================================================================
    // Encoder recurrence: 3 independent block groups, group barrier/step
    // =====================================================================
    {
        const int e    = bid % 3;
        const int rank = bid / 3;
        const unsigned cnt = (unsigned)((nblk - e + 2) / 3);
        const int TWg  = (int)cnt * NWARP;
        const int gwg  = rank * NWARP + warp;
        unsigned genG = ldacq(&g_grel[e * 64]);

        for (int t = 0; t < L; t++) {
            const int cur = t & 1, nxt = cur ^ 1;
            for (int k = tid; k < H; k += TPB) sm[OFF_H + k] = __ldcg(&g_eh[cur][e * H + k]);
            __syncthreads();
            for (int i = gwg; i < H; i += TWg) {
                const float* base = enc_W_hh + (size_t)e * 3 * H * H;
                const float4* wr = (const float4*)(base + (size_t)i * H);
                const float4* wz = (const float4*)(base + (size_t)(H + i) * H);
                const float4* wn = (const float4*)(base + (size_t)(2 * H + i) * H);
                const float4* hv = (const float4*)(sm + OFF_H);
                float ar = 0.f, az = 0.f, an = 0.f;
                for (int k4 = lane; k4 < H / 4; k4 += 32) {
                    float4 h4 = hv[k4];
                    float4 a = __ldg(&wr[k4]); ar += a.x*h4.x + a.y*h4.y + a.z*h4.z + a.w*h4.w;
                    float4 b = __ldg(&wz[k4]); az += b.x*h4.x + b.y*h4.y + b.z*h4.z + b.w*h4.w;
                    float4 c = __ldg(&wn[k4]); an += c.x*h4.x + c.y*h4.y + c.z*h4.z + c.w*h4.w;
                }
                ar = wredsum(ar); az = wredsum(az); an = wredsum(an);
                if (lane == 0) {
                    const int row = e * 3 * H;
                    float gir = __ldcg(&g_gi[((size_t)row + i) * L + t]);
                    float giz = __ldcg(&g_gi[((size_t)row + H + i) * L + t]);
                    float gin = __ldcg(&g_gi[((size_t)row + 2 * H + i) * L + t]);
                    float ghr = ar + __ldg(&enc_b_hh[row + i]);
                    float ghz = az + __ldg(&enc_b_hh[row + H + i]);
                    float ghn = an + __ldg(&enc_b_hh[row + 2 * H + i]);
                    float rg = sigm(gir + ghr);
                    float zg = sigm(giz + ghz);
                    float ng = tanhf(gin + rg * ghn);
                    float hp = sm[OFF_H + i];
                    float hn2 = (1.f - zg) * ng + zg * hp;
                    g_eh[nxt][e * H + i] = hn2;
                    g_hist[((size_t)e * L + t) * H + i] = hn2;
                }
            }
            gbar_grp(genG, e, cnt);
        }
    }
    gbar(gen, nblk, bid);

    // ============== enc_outs = hist0 + (hist1 + hist2)/2 ==============
    for (int i = bid * TPB + tid; i < L * H; i += nblk * TPB)
        g_eo[i] = __ldcg(&g_hist[i]) +
                  0.5f * (__ldcg(&g_hist[L * H + i]) + __ldcg(&g_hist[2 * L * H + i]));
    gbar(gen, nblk, bid);

    // ============== M[j][l] = W_comb[j, H:2H] . enc_outs[l] ==============
    {
        const int mrpb = (H + nblk - 1) / nblk;
        const int j0 = bid * mrpb, j1 = min(H, j0 + mrpb);
        for (int p = 0; p < 2; p++) {
            __syncthreads();
            for (int idx = tid; idx < 32 * H; idx += TPB) {
                int tt = idx >> 10, k = idx & (H - 1);
                sm[tt * TILE_STRIDE + k] = __ldcg(&g_eo[(size_t)(p * 32 + tt) * H + k]);
            }
            __syncthreads();
            for (int j = j0 + warp; j < j1; j += NWARP) {
                const float4* w4 = (const float4*)(W_comb + (size_t)j * 2 * H + H);
                const float* xs = sm + lane * TILE_STRIDE;
                float acc = 0.f;
#pragma unroll 4
                for (int k4 = 0; k4 < H / 4; k4++) {
                    float4 w = __ldg(&w4[k4]);
                    int k = k4 * 4;
                    acc += w.x * xs[k] + w.y * xs[k + 1] + w.z * xs[k + 2] + w.w * xs[k + 3];
                }
                g_M[j * L + p * 32 + lane] = acc;
            }
        }
    }
    gbar(gen, nblk, bid);

    // =================== blocks >= dblk are done ===================
    if (bid >= dblk) return;

    // =====================================================================
    // Greedy attention decode on dblk blocks: 64 steps x 4 barriers
    // =====================================================================
    const int TWd = dblk * NWARP;
    const int RPBV = (V + dblk - 1) / dblk;
    const int vr0 = bid * RPBV, vr1 = min(V, vr0 + RPBV);

    for (int k = tid; k < H; k += TPB) sm[OFF_H + k] = 0.f;
    {
        float mn = 0.f;
        for (int r = vr0 + tid; r < vr1; r += TPB) mn = fmaxf(mn, __ldcg(&g_wn[r]));
#pragma unroll
        for (int o = 16; o; o >>= 1) mn = fmaxf(mn, __shfl_xor_sync(0xffffffffu, mn, o));
        if (lane == 0) sm[OFF_SRED + 128 + warp] = mn;
        __syncthreads();
        if (tid == 0) {
            float m = 0.f;
            for (int w = 0; w < NWARP; w++) m = fmaxf(m, sm[OFF_SRED + 128 + w]);
            sm[OFF_BMN] = m;
        }
    }
    __syncthreads();

    for (int t = 0; t < L; t++) {
        // ---- pre: warp0 reduces prev step's exact argmax + approx sumexp ----
        if (t == 0) {
            if (tid == 0) { st_i[0] = 0; st_i[1] = 0; }
        } else if (warp == 0) {
            float s = 0.f; unsigned long long bk = 0ull;
            for (int b = lane; b < dblk; b += 32) {
                s += __ldcg(&g_sums[b]);
                unsigned long long k = __ldcg(&g_keys[b]);
                if (k > bk) bk = k;
            }
            s = wredsum(s);
#pragma unroll
            for (int o = 16; o; o >>= 1) {
                unsigned long long k = __shfl_down_sync(0xffffffffu, bk, o);
                if (k > bk) bk = k;
            }
            if (lane == 0) {
                int nxtTok = (int)(~(unsigned)(bk & 0xffffffffu));
                int done = st_i[1];
                st_i[0] = done ? st_i[0] : nxtTok;
                st_i[1] = done | (nxtTok == EOS_TOK);
                sm[OFF_LSEH + (t - 1)] = logf(s);
                if (bid == 0) out[OUT_TOK + (t - 1)] = (float)st_i[0];
            }
        }
        __syncthreads();
        // stage e
        {
            int tok = st_i[0];
            for (int k = tid; k < H; k += TPB)
                sm[OFF_E + k] = __ldg(&dec_emb[(size_t)tok * H + k]);
        }
        __syncthreads();

        // ---- S1: attn scores / C1 / hh-dots (2112 units over TWd warps) ----
        for (int u = gw; u < 64 + 2 * H; u += TWd) {
            if (u < 64) {
                const int l = u;
                const float4* w4 = (const float4*)(W_attn + (size_t)l * 2 * H);
                const float4* e4 = (const float4*)(sm + OFF_E);
                const float4* h4 = (const float4*)(sm + OFF_H);
                float acc = 0.f;
                for (int k4 = lane; k4 < H / 4; k4 += 32) {
                    float4 w = __ldg(&w4[k4]);        float4 x = e4[k4];
                    acc += w.x*x.x + w.y*x.y + w.z*x.z + w.w*x.w;
                }
                for (int k4 = lane; k4 < H / 4; k4 += 32) {
                    float4 w = __ldg(&w4[H / 4 + k4]); float4 x = h4[k4];
                    acc += w.x*x.x + w.y*x.y + w.z*x.z + w.w*x.w;
                }
                acc = wredsum(acc);
                if (lane == 0) g_s[l] = acc + __ldg(&b_attn[l]);
            } else if (u < 64 + H) {
                const int j = u - 64;
                const float4* w4 = (const float4*)(W_comb + (size_t)j * 2 * H);
                const float4* e4 = (const float4*)(sm + OFF_E);
                float acc = 0.f;
                for (int k4 = lane; k4 < H / 4; k4 += 32) {
                    float4 w = __ldg(&w4[k4]); float4 x = e4[k4];
                    acc += w.x*x.x + w.y*x.y + w.z*x.z + w.w*x.w;
                }
                acc = wredsum(acc);
                if (lane == 0) g_c1[j] = acc + __ldg(&b_comb[j]);
            } else {
                const int i = u - 64 - H;
                const float4* w0 = (const float4*)(dec_W_hh + (size_t)i * H);
                const float4* w1 = (const float4*)(dec_W_hh + (size_t)(H + i) * H);
                const float4* w2 = (const float4*)(dec_W_hh + (size_t)(2 * H + i) * H);
                const float4* vv = (const float4*)(sm + OFF_H);
                float a0 = 0.f, a1 = 0.f, a2 = 0.f;
                for (int k4 = lane; k4 < H / 4; k4 += 32) {
                    float4 x4 = vv[k4], w;
                    w = __ldg(&w0[k4]); a0 += w.x*x4.x + w.y*x4.y + w.z*x4.z + w.w*x4.w;
                    w = __ldg(&w1[k4]); a1 += w.x*x4.x + w.y*x4.y + w.z*x4.z + w.w*x4.w;
                    w = __ldg(&w2[k4]); a2 += w.x*x4.x + w.y*x4.y + w.z*x4.z + w.w*x4.w;
                }
                a0 = wredsum(a0); a1 = wredsum(a1); a2 = wredsum(a2);
                if (lane == 0) {
                    float* p = g_part + i * 8 + 3;
                    p[0] = a0; p[1] = a1; p[2] = a2;
                }
            }
        }
        gbar(gen, dblk, bid);

        // ---- S2: warp-parallel softmax; x[j] = relu(C1[j] + M[j,:].aw) ----
        if (warp == 0) {
            float v0 = __ldcg(&g_s[lane]);
            float v1 = __ldcg(&g_s[lane + 32]);
            float m = fmaxf(v0, v1);
#pragma unroll
            for (int o = 16; o; o >>= 1) m = fmaxf(m, __shfl_xor_sync(0xffffffffu, m, o));
            float e0 = expf(v0 - m), e1 = expf(v1 - m);
            float s = e0 + e1;
#pragma unroll
            for (int o = 16; o; o >>= 1) s += __shfl_xor_sync(0xffffffffu, s, o);
            float inv = 1.f / s;
            sm[OFF_AW + lane] = e0 * inv;
            sm[OFF_AW + lane + 32] = e1 * inv;
        }
        __syncthreads();
        if (bid == 0 && tid < 64) out[OUT_ATT + t * 64 + tid] = sm[OFF_AW + tid];
        for (int j = gw; j < H; j += TWd) {
            float a = sm[OFF_AW + lane]      * __ldcg(&g_M[j * L + lane]) +
                      sm[OFF_AW + lane + 32] * __ldcg(&g_M[j * L + lane + 32]);
            a = wredsum(a);
            if (lane == 0) g_x[j] = fmaxf(0.f, a + __ldcg(&g_c1[j]));
        }
        gbar(gen, dblk, bid);

        // ---- S3: ih-dots ----
        for (int k = tid; k < H; k += TPB) sm[OFF_X + k] = __ldcg(&g_x[k]);
        __syncthreads();
        for (int i = gw; i < H; i += TWd) {
            const float4* w0 = (const float4*)(dec_W_ih + (size_t)i * H);
            const float4* w1 = (const float4*)(dec_W_ih + (size_t)(H + i) * H);
            const float4* w2 = (const float4*)(dec_W_ih + (size_t)(2 * H + i) * H);
            const float4* vv = (const float4*)(sm + OFF_X);
            float a0 = 0.f, a1 = 0.f, a2 = 0.f;
            for (int k4 = lane; k4 < H / 4; k4 += 32) {
                float4 x4 = vv[k4], w;
                w = __ldg(&w0[k4]); a0 += w.x*x4.x + w.y*x4.y + w.z*x4.z + w.w*x4.w;
                w = __ldg(&w1[k4]); a1 += w.x*x4.x + w.y*x4.y + w.z*x4.z + w.w*x4.w;
                w = __ldg(&w2[k4]); a2 += w.x*x4.x + w.y*x4.y + w.z*x4.z + w.w*x4.w;
            }
            a0 = wredsum(a0); a1 = wredsum(a1); a2 = wredsum(a2);
            if (lane == 0) {
                float* p = g_part + i * 8;
                p[0] = a0; p[1] = a1; p[2] = a2;
            }
        }
        gbar(gen, dblk, bid);

        // ---- S4 prologue: gates -> h2, frozen h, ||h2|| (every block) ----
        {
            float sq = 0.f;
            for (int i = tid; i < H; i += TPB) {
                const float* p = g_part + i * 8;
                float gir = __ldcg(&p[0]) + __ldg(&dec_b_ih[i]);
                float giz = __ldcg(&p[1]) + __ldg(&dec_b_ih[H + i]);
                float gin = __ldcg(&p[2]) + __ldg(&dec_b_ih[2 * H + i]);
                float ghr = __ldcg(&p[3]) + __ldg(&dec_b_hh[i]);
                float ghz = __ldcg(&p[4]) + __ldg(&dec_b_hh[H + i]);
                float ghn = __ldcg(&p[5]) + __ldg(&dec_b_hh[2 * H + i]);
                float rg = sigm(gir + ghr);
                float zg = sigm(giz + ghz);
                float ng = tanhf(gin + rg * ghn);
                float hp = sm[OFF_H + i];
                float h2 = (1.f - zg) * ng + zg * hp;
                sm[OFF_H2 + i] = h2;
                sm[OFF_H + i]  = st_i[1] ? hp : h2;
                sq += h2 * h2;
            }
            sq = wredsum(sq);
            if (lane == 0) sm[OFF_SRED + 128 + warp] = sq;
        }
        __syncthreads();
        if (tid == 0) {
            float s = 0.f;
            for (int w = 0; w < NWARP; w++) s += sm[OFF_SRED + 128 + w];
            sm[OFF_HN] = sqrtf(s);
            ((int*)(sm + OFF_CCNT))[0] = 0;
        }
        __syncthreads();

        // ---- S4 main: bf16 logits, 2 rows per warp-iteration ----
        {
            float wsum = 0.f, wmaxv = -3.4e38f;
            const float4* hv = (const float4*)(sm + OFF_H2);
            for (int r = vr0 + (warp << 1); r < vr1; r += (NWARP << 1)) {
                const bool two = (r + 1 < vr1);
                const uint4* wb0 = (const uint4*)(g_Wbf + (size_t)r * H);
                const uint4* wb1 = (const uint4*)(g_Wbf + (size_t)(r + 1) * H);
                float acc0 = 0.f, acc1 = 0.f;
#pragma unroll
                for (int j = 0; j < 4; j++) {
                    uint4 w0v = __ldg(&wb0[j * 32 + lane]);
                    uint4 w1v = two ? __ldg(&wb1[j * 32 + lane]) : make_uint4(0u, 0u, 0u, 0u);
                    int hu = (j * 32 + lane) * 2;
                    float4 hA = hv[hu], hB = hv[hu + 1];
                    float2 f0 = bf2f(w0v.x), f1 = bf2f(w0v.y);
                    float2 f2 = bf2f(w0v.z), f3 = bf2f(w0v.w);
                    acc0 += f0.x*hA.x + f0.y*hA.y + f1.x*hA.z + f1.y*hA.w
                          + f2.x*hB.x + f2.y*hB.y + f3.x*hB.z + f3.y*hB.w;
                    float2 g0 = bf2f(w1v.x), g1 = bf2f(w1v.y);
                    float2 g2 = bf2f(w1v.z), g3 = bf2f(w1v.w);
                    acc1 += g0.x*hA.x + g0.y*hA.y + g1.x*hA.z + g1.y*hA.w
                          + g2.x*hB.x + g2.y*hB.y + g3.x*hB.z + g3.y*hB.w;
                }
                acc0 = wredsum(acc0); acc1 = wredsum(acc1);
                if (lane == 0) {
                    float l0 = acc0 + __ldg(&b_out[r]);
                    out[(size_t)t * V + r] = l0;
                    wsum += expf(l0);
                    wmaxv = fmaxf(wmaxv, l0);
                    if (two) {
                        float l1 = acc1 + __ldg(&b_out[r + 1]);
                        out[(size_t)t * V + r + 1] = l1;
                        wsum += expf(l1);
                        wmaxv = fmaxf(wmaxv, l1);
                    }
                }
            }
            __syncthreads();
            if (lane == 0) {
                sm[OFF_SRED + warp]      = wsum;
                sm[OFF_SRED + 64 + warp] = wmaxv;
            }
            __syncthreads();
            if (tid == 0) {
                float bs = 0.f, bm = -3.4e38f;
                for (int w = 0; w < NWARP; w++) {
                    bs += sm[OFF_SRED + w];
                    bm = fmaxf(bm, sm[OFF_SRED + 64 + w]);
                }
                g_sums[bid] = bs;
                sm[OFF_BMAX] = bm;
            }
            __syncthreads();

            // ---- refine: exact fp32 recompute of candidate rows ----
            {
                float Emax = EFAC * sm[OFF_BMN] * sm[OFF_HN];
                float thr = sm[OFF_BMAX] - (2.f * Emax + 1e-7f);
                int* ccnt = (int*)(sm + OFF_CCNT);
                int* cand = (int*)(sm + OFF_CAND);
                size_t base = (size_t)t * V;
                for (int r = vr0 + tid; r < vr1; r += TPB) {
                    if (out[base + r] >= thr) {
                        int idx = atomicAdd(ccnt, 1);
                        cand[idx] = r;          // nc <= RPBV(422) < 512 always
                    }
                }
                __syncthreads();
                int nc = *ccnt;
                unsigned long long wkey = 0ull;
                for (int c = warp; c < nc; c += NWARP) {
                    int r = cand[c];
                    const float4* w4 = (const float4*)(W_out + (size_t)r * H);
                    float acc = 0.f;
#pragma unroll 2
                    for (int k4 = lane; k4 < H / 4; k4 += 32) {
                        float4 w = __ldg(&w4[k4]); float4 h4 = hv[k4];
                        acc += w.x*h4.x + w.y*h4.y + w.z*h4.z + w.w*h4.w;
                    }
                    acc = wredsum(acc);
                    if (lane == 0) {
                        unsigned long long k = packkey(acc + __ldg(&b_out[r]), r);
                        if (k > wkey) wkey = k;
                    }
                }
                if (lane == 0) ((unsigned long long*)(sm + OFF_KRED))[warp] = wkey;
                __syncthreads();
                if (tid == 0) {
                    unsigned long long bk = 0ull;
                    for (int w = 0; w < NWARP; w++) {
                        unsigned long long k = ((unsigned long long*)(sm + OFF_KRED))[w];
                        if (k > bk) bk = k;
                    }
                    g_keys[bid] = bk;
                }
            }
        }
        gbar(gen, dblk, bid);
    }

    // ---- final: reduce last step; write last token; epilogue lse subtract ----
    if (warp == 0) {
        float s = 0.f; unsigned long long bk = 0ull;
        for (int b = lane; b < dblk; b += 32) {
            s += __ldcg(&g_sums[b]);
            unsigned long long k = __ldcg(&g_keys[b]);
            if (k > bk) bk = k;
        }
        s = wredsum(s);
#pragma unroll
        for (int o = 16; o; o >>= 1) {
            unsigned long long k = __shfl_down_sync(0xffffffffu, bk, o);
            if (k > bk) bk = k;
        }
        if (lane == 0) {
            int nxtTok = (int)(~(unsigned)(bk & 0xffffffffu));
            int done = st_i[1];
            st_i[0] = done ? st_i[0] : nxtTok;
            sm[OFF_LSEH + (L - 1)] = logf(s);
            if (bid == 0) out[OUT_TOK + (L - 1)] = (float)st_i[0];
        }
    }
    __syncthreads();
    for (int t = 0; t < L; t++) {
        float lse = sm[OFF_LSEH + t];
        size_t base = (size_t)t * V;
        for (int r = vr0 + tid; r < vr1; r += TPB)
            out[base + r] = out[base + r] - lse;
    }
}

// ------------------------- launch -------------------------
extern "C" void kernel_launch(void* const* d_in, const int* in_sizes, int n_in,
                              void* d_out, int out_size) {
    (void)in_sizes; (void)n_in; (void)out_size;
    int dev = 0; cudaGetDevice(&dev);
    int sms = 0; cudaDeviceGetAttribute(&sms, cudaDevAttrMultiProcessorCount, dev);
    if (sms < 1) sms = 148;
    int nblk = sms > 256 ? 256 : sms;

    size_t smemB = (size_t)SMEM_FLOATS * sizeof(float);
    cudaFuncSetAttribute(ms2s_kernel, cudaFuncAttributeMaxDynamicSharedMemorySize, (int)smemB);

    ms2s_kernel<<<nblk, TPB, smemB>>>(
        (const int*)d_in[0],   (const int*)d_in[1],
        (const float*)d_in[2], (const float*)d_in[3], (const float*)d_in[4],
        (const float*)d_in[5], (const float*)d_in[6],
        (const float*)d_in[7], (const float*)d_in[8], (const float*)d_in[9],
        (const float*)d_in[10], (const float*)d_in[11],
        (const float*)d_in[12], (const float*)d_in[13], (const float*)d_in[14],
        (const float*)d_in[15], (const float*)d_in[16], (const float*)d_in[17],
        (float*)d_out, nblk);
}

// round 16
// speedup vs baseline: 1.2591x; 1.2591x over previous
#include <cuda_runtime.h>
#include <cuda_bf16.h>
#include <cstdint>
#include <cstddef>

#define H 1024
#define V 32000
#define L 64
#define NEC 3
#define TPB 512
#define NWARP 16
#define EOS_TOK 1

#define TILE_STRIDE 1025
#define SMEM_FLOATS (32 * TILE_STRIDE + 64)

// decode-area smem offsets (in floats)
#define OFF_E    0
#define OFF_H    1024
#define OFF_X    4096
#define OFF_H2   5120
#define OFF_AW   6144
#define OFF_SRED 6208
#define OFF_KRED 6464   /* ull[128] -> 256 floats */
#define OFF_ST   6976   /* int[2]: tok, done */
#define OFF_BMAX 6981
#define OFF_HN   6982
#define OFF_BMN  6983
#define OFF_CCNT 6984   /* int */
#define OFF_CAND 6992   /* int[512] */
#define OFF_LSEH 7600   /* float[64] lse history */

#define EFAC 0.004f

#define OUT_ATT  (L * V)
#define OUT_TOK  (L * V + L * L)

// ------------------------- device scratch (static; no allocs) -------------------------
__device__ float g_gi[(size_t)NEC * 3 * H * L];   // [e][row][t]
__device__ float g_hist[(size_t)NEC * L * H];
__device__ float g_eo[L * H];
__device__ float g_M[H * L];                      // [j][l]
__device__ float g_epart[NEC * 3 * H];            // encoder gate-dot partials
__device__ float g_part[H * 8];                   // decode: [i]: 0..2 ih, 3..5 hh
__device__ float g_s[L];
__device__ float g_c1[H];
__device__ float g_x[H];
__device__ float g_wn[V];                         // row norms of W_out (bf16 copy)
__device__ __nv_bfloat16 g_Wbf[(size_t)V * H];    // bf16 copy of W_out
__device__ unsigned long long g_keys[256];
__device__ float g_sums[256];

// tree barrier state — FENCE-FREE protocol (no __threadfence -> no L1D flush)
__device__ unsigned g_arrL[8 * 64];
__device__ unsigned g_arrM = 0;
__device__ unsigned g_release = 0;
__device__ unsigned g_garr[3 * 64];
__device__ unsigned g_grel[3 * 64];

// ------------------------- helpers -------------------------
__device__ __forceinline__ unsigned ldacq(const unsigned* p) {
    unsigned v;
    asm volatile("ld.acquire.gpu.global.u32 %0, [%1];" : "=r"(v) : "l"(p) : "memory");
    return v;
}
__device__ __forceinline__ void strel(unsigned* p, unsigned v) {
    asm volatile("st.release.gpu.global.u32 [%0], %1;" :: "l"(p), "r"(v) : "memory");
}
__device__ __forceinline__ void strelax(unsigned* p, unsigned v) {
    asm volatile("st.relaxed.gpu.global.u32 [%0], %1;" :: "l"(p), "r"(v) : "memory");
}
__device__ __forceinline__ unsigned atom_add_acqrel(unsigned* p, unsigned v) {
    unsigned r;
    asm volatile("atom.acq_rel.gpu.global.add.u32 %0, [%1], %2;"
                 : "=r"(r) : "l"(p), "r"(v) : "memory");
    return r;
}

__device__ __forceinline__ float wredsum(float v) {
#pragma unroll
    for (int o = 16; o; o >>= 1) v += __shfl_down_sync(0xffffffffu, v, o);
    return v;
}

__device__ __forceinline__ unsigned long long packkey(float v, int r) {
    unsigned u = __float_as_uint(v);
    u = (u & 0x80000000u) ? ~u : (u | 0x80000000u);
    return ((unsigned long long)u << 32) | (unsigned)(~(unsigned)r);
}

__device__ __forceinline__ float sigm(float x) { return 1.f / (1.f + expf(-x)); }

__device__ __forceinline__ float2 bf2f(unsigned u) {
    __nv_bfloat162 t = *reinterpret_cast<__nv_bfloat162*>(&u);
    return __bfloat1622float2(t);
}

// two-level grid barrier (8 leaves), fence-free; all CTAs resident (1 CTA/SM)
__device__ __forceinline__ void gbar(unsigned& gen, int nb, int bid) {
    __syncthreads();
    if (threadIdx.x == 0) {
        const int leaf = bid & 7;
        const unsigned lcnt = (unsigned)((nb - leaf + 7) >> 3);
        unsigned t = atom_add_acqrel(&g_arrL[leaf * 64], 1u);
        if (t == lcnt - 1u) {
            strelax(&g_arrL[leaf * 64], 0u);
            unsigned m = atom_add_acqrel(&g_arrM, 1u);
            if (m == 7u) {
                strelax(&g_arrM, 0u);
                strel(&g_release, gen + 1u);
            } else {
                while (ldacq(&g_release) == gen) { }
            }
        } else {
            while (ldacq(&g_release) == gen) { }
        }
    }
    gen++;
    __syncthreads();
}

// group barrier for one encoder's block set (fence-free)
__device__ __forceinline__ void gbar_grp(unsigned& gen, int e, unsigned cnt) {
    __syncthreads();
    if (threadIdx.x == 0) {
        unsigned t = atom_add_acqrel(&g_garr[e * 64], 1u);
        if (t == cnt - 1u) {
            strelax(&g_garr[e * 64], 0u);
            strel(&g_grel[e * 64], gen + 1u);
        } else {
            while (ldacq(&g_grel[e * 64]) == gen) { }
        }
    }
    gen++;
    __syncthreads();
}

// ------------------------- kernel -------------------------
__global__ void __launch_bounds__(TPB, 1)
ms2s_kernel(const int* __restrict__ q_ids,
            const int* __restrict__ cand_ids,
            const float* __restrict__ enc_emb,
            const float* __restrict__ enc_W_ih,
            const float* __restrict__ enc_W_hh,
            const float* __restrict__ enc_b_ih,
            const float* __restrict__ enc_b_hh,
            const float* __restrict__ dec_emb,
            const float* __restrict__ W_attn,
            const float* __restrict__ b_attn,
            const float* __restrict__ W_comb,
            const float* __restrict__ b_comb,
            const float* __restrict__ dec_W_ih,
            const float* __restrict__ dec_W_hh,
            const float* __restrict__ dec_b_ih,
            const float* __restrict__ dec_b_hh,
            const float* __restrict__ W_out,
            const float* __restrict__ b_out,
            float* __restrict__ out,
            int nblk)
{
    extern __shared__ float sm[];
    const int tid  = threadIdx.x;
    const int warp = tid >> 5;
    const int lane = tid & 31;
    const int bid  = blockIdx.x;
    const int gw   = bid * NWARP + warp;
    const int TW   = nblk * NWARP;
    int* st_i = (int*)(sm + OFF_ST);

    unsigned gen = ldacq(&g_release);

    // =====================================================================
    // Setup: zero enc hidden partials; fused bf16-convert + row-norm of
    // W_out (one read of 134 MB); gi = W_ih@x + b_ih
    // =====================================================================
    const int RPBV = (V + nblk - 1) / nblk;
    const int vr0 = bid * RPBV, vr1 = min(V, vr0 + RPBV);

    // fused conversion + norms: warp per row within this block's row range
    for (int r = vr0 + warp; r < vr1; r += NWARP) {
        const float4* src = (const float4*)(W_out + (size_t)r * H);
        uint2* dst = (uint2*)(g_Wbf + (size_t)r * H);
        float ss = 0.f;
#pragma unroll
        for (int k4 = lane; k4 < 256; k4 += 32) {
            float4 a = __ldg(&src[k4]);
            ss += a.x*a.x + a.y*a.y + a.z*a.z + a.w*a.w;
            unsigned short s0 = __bfloat16_as_ushort(__float2bfloat16_rn(a.x));
            unsigned short s1 = __bfloat16_as_ushort(__float2bfloat16_rn(a.y));
            unsigned short s2 = __bfloat16_as_ushort(__float2bfloat16_rn(a.z));
            unsigned short s3 = __bfloat16_as_ushort(__float2bfloat16_rn(a.w));
            uint2 o;
            o.x = (unsigned)s0 | ((unsigned)s1 << 16);
            o.y = (unsigned)s2 | ((unsigned)s3 << 16);
            dst[k4] = o;
        }
        ss = wredsum(ss);
        if (lane == 0) g_wn[r] = sqrtf(ss);
    }
    for (int i = bid * TPB + tid; i < NEC * 3 * H; i += nblk * TPB) g_epart[i] = 0.f;

    {
        const int be   = bid % 3;
        const int rank = bid / 3;
        const int cnt  = (nblk - be + 2) / 3;
        const int rpb  = (3 * H + cnt - 1) / cnt;
        const int r0   = rank * rpb;
        const int r1   = min(3 * H, r0 + rpb);
        int* ids_s = (int*)(sm + 32 * TILE_STRIDE);
        const float* Wih = enc_W_ih + (size_t)be * 3 * H * H;
        const float* emb = enc_emb + (size_t)be * V * H;

        for (int p = 0; p < 2; p++) {
            __syncthreads();
            if (tid < 32) {
                int tIdx = p * 32 + tid;
                ids_s[tid] = (be == 0) ? q_ids[tIdx] : cand_ids[(be - 1) * L + tIdx];
            }
            __syncthreads();
            for (int idx = tid; idx < 32 * H; idx += TPB) {
                int tt = idx >> 10, k = idx & (H - 1);
                sm[tt * TILE_STRIDE + k] = __ldg(&emb[(size_t)ids_s[tt] * H + k]);
            }
            __syncthreads();
            for (int r = r0 + warp; r < r1; r += NWARP) {
                const float4* w4 = (const float4*)(Wih + (size_t)r * H);
                const float* xs = sm + lane * TILE_STRIDE;
                float acc = 0.f;
#pragma unroll 4
                for (int k4 = 0; k4 < H / 4; k4++) {
                    float4 w = __ldg(&w4[k4]);
                    int k = k4 * 4;
                    acc += w.x * xs[k] + w.y * xs[k + 1] + w.z * xs[k + 2] + w.w * xs[k + 3];
                }
                g_gi[((size_t)be * 3 * H + r) * L + p * 32 + lane] =
                    acc + __ldg(&enc_b_ih[be * 3 * H + r]);
            }
        }
    }
    gbar(gen, nblk, bid);

    // =====================================================================
    // Encoder recurrence: single-dot units + redundant gate prologue.
    // Phase t: [prologue: h_t from dots_{t-1} + gi_{t-1} (t>0)] then
    //          dots_t = W_hh@h_t (3072 one-dot units). 1 group barrier/phase.
    // =====================================================================
    {
        const int e    = bid % 3;
        const int rank = bid / 3;
        const unsigned cnt = (unsigned)((nblk - e + 2) / 3);
        const int TWg  = (int)cnt * NWARP;
        const int gwg  = rank * NWARP + warp;
        unsigned genG = ldacq(&g_grel[e * 64]);
        const float* Whh = enc_W_hh + (size_t)e * 3 * H * H;
        const float* bhh = enc_b_hh + e * 3 * H;
        const float* ep  = g_epart + e * 3 * H;

        for (int k = tid; k < H; k += TPB) sm[OFF_H + k] = 0.f;   // h_0 = 0
        __syncthreads();

        for (int t = 0; t < L; t++) {
            if (t > 0) {
                for (int i = tid; i < H; i += TPB) {
                    float ar = __ldcg(&ep[i]);
                    float az = __ldcg(&ep[H + i]);
                    float an = __ldcg(&ep[2 * H + i]);
                    const size_t gbase = ((size_t)e * 3 * H + i) * L + (t - 1);
                    float gir = __ldcg(&g_gi[gbase]);
                    float giz = __ldcg(&g_gi[gbase + (size_t)H * L]);
                    float gin = __ldcg(&g_gi[gbase + (size_t)2 * H * L]);
                    float ghr = ar + __ldg(&bhh[i]);
                    float ghz = az + __ldg(&bhh[H + i]);
                    float ghn = an + __ldg(&bhh[2 * H + i]);
                    float rg = sigm(gir + ghr);
                    float zg = sigm(giz + ghz);
                    float ng = tanhf(gin + rg * ghn);
                    float hp = sm[OFF_H + i];
                    float hn2 = (1.f - zg) * ng + zg * hp;
                    sm[OFF_H + i] = hn2;
                    if (rank == 0) g_hist[((size_t)e * L + (t - 1)) * H + i] = hn2;
                }
                __syncthreads();
            }
            // dots_t: one dot per unit, 3072 units
            for (int u = gwg; u < 3 * H; u += TWg) {
                const float4* w4 = (const float4*)(Whh + (size_t)u * H);
                const float4* hv = (const float4*)(sm + OFF_H);
                float acc = 0.f;
                for (int k4 = lane; k4 < H / 4; k4 += 32) {
                    float4 w = __ldg(&w4[k4]); float4 h4 = hv[k4];
                    acc += w.x*h4.x + w.y*h4.y + w.z*h4.z + w.w*h4.w;
                }
                acc = wredsum(acc);
                if (lane == 0) g_epart[e * 3 * H + u] = acc;
            }
            gbar_grp(genG, e, cnt);
        }
        // epilogue: h_L from dots_{L-1}; write hist[L-1]
        for (int i = tid; i < H; i += TPB) {
            float ar = __ldcg(&ep[i]);
            float az = __ldcg(&ep[H + i]);
            float an = __ldcg(&ep[2 * H + i]);
            const size_t gbase = ((size_t)e * 3 * H + i) * L + (L - 1);
            float gir = __ldcg(&g_gi[gbase]);
            float giz = __ldcg(&g_gi[gbase + (size_t)H * L]);
            float gin = __ldcg(&g_gi[gbase + (size_t)2 * H * L]);
            float ghr = ar + __ldg(&bhh[i]);
            float ghz = az + __ldg(&bhh[H + i]);
            float ghn = an + __ldg(&bhh[2 * H + i]);
            float rg = sigm(gir + ghr);
            float zg = sigm(giz + ghz);
            float ng = tanhf(gin + rg * ghn);
            float hp = sm[OFF_H + i];
            float hn2 = (1.f - zg) * ng + zg * hp;
            if (rank == 0) g_hist[((size_t)e * L + (L - 1)) * H + i] = hn2;
        }
    }
    gbar(gen, nblk, bid);

    // ============== enc_outs = hist0 + (hist1 + hist2)/2 ==============
    for (int i = bid * TPB + tid; i < L * H; i += nblk * TPB)
        g_eo[i] = __ldcg(&g_hist[i]) +
                  0.5f * (__ldcg(&g_hist[L * H + i]) + __ldcg(&g_hist[2 * L * H + i]));
    gbar(gen, nblk, bid);

    // ============== M[j][l] = W_comb[j, H:2H] . enc_outs[l] ==============
    {
        const int mrpb = (H + nblk - 1) / nblk;
        const int j0 = bid * mrpb, j1 = min(H, j0 + mrpb);
        for (int p = 0; p < 2; p++) {
            __syncthreads();
            for (int idx = tid; idx < 32 * H; idx += TPB) {
                int tt = idx >> 10, k = idx & (H - 1);
                sm[tt * TILE_STRIDE + k] = __ldcg(&g_eo[(size_t)(p * 32 + tt) * H + k]);
            }
            __syncthreads();
            for (int j = j0 + warp; j < j1; j += NWARP) {
                const float4* w4 = (const float4*)(W_comb + (size_t)j * 2 * H + H);
                const float* xs = sm + lane * TILE_STRIDE;
                float acc = 0.f;
#pragma unroll 4
                for (int k4 = 0; k4 < H / 4; k4++) {
                    float4 w = __ldg(&w4[k4]);
                    int k = k4 * 4;
                    acc += w.x * xs[k] + w.y * xs[k + 1] + w.z * xs[k + 2] + w.w * xs[k + 3];
                }
                g_M[j * L + p * 32 + lane] = acc;
            }
        }
    }
    gbar(gen, nblk, bid);

    // =====================================================================
    // Greedy attention decode: 64 steps x 4 barriers (R13 structure)
    // =====================================================================
    for (int k = tid; k < H; k += TPB) sm[OFF_H + k] = 0.f;
    {
        float mn = 0.f;
        for (int r = vr0 + tid; r < vr1; r += TPB) mn = fmaxf(mn, __ldcg(&g_wn[r]));
#pragma unroll
        for (int o = 16; o; o >>= 1) mn = fmaxf(mn, __shfl_xor_sync(0xffffffffu, mn, o));
        if (lane == 0) sm[OFF_SRED + 128 + warp] = mn;
        __syncthreads();
        if (tid == 0) {
            float m = 0.f;
            for (int w = 0; w < NWARP; w++) m = fmaxf(m, sm[OFF_SRED + 128 + w]);
            sm[OFF_BMN] = m;
        }
    }
    __syncthreads();

    for (int t = 0; t < L; t++) {
        // ---- pre: warp0 reduces prev step's exact argmax + approx sumexp ----
        if (t == 0) {
            if (tid == 0) { st_i[0] = 0; st_i[1] = 0; }
        } else if (warp == 0) {
            float s = 0.f; unsigned long long bk = 0ull;
            for (int b = lane; b < nblk; b += 32) {
                s += __ldcg(&g_sums[b]);
                unsigned long long k = __ldcg(&g_keys[b]);
                if (k > bk) bk = k;
            }
            s = wredsum(s);
#pragma unroll
            for (int o = 16; o; o >>= 1) {
                unsigned long long k = __shfl_down_sync(0xffffffffu, bk, o);
                if (k > bk) bk = k;
            }
            if (lane == 0) {
                int nxtTok = (int)(~(unsigned)(bk & 0xffffffffu));
                int done = st_i[1];
                st_i[0] = done ? st_i[0] : nxtTok;
                st_i[1] = done | (nxtTok == EOS_TOK);
                sm[OFF_LSEH + (t - 1)] = logf(s);
                if (bid == 0) out[OUT_TOK + (t - 1)] = (float)st_i[0];
            }
        }
        __syncthreads();
        // stage e
        {
            int tok = st_i[0];
            for (int k = tid; k < H; k += TPB)
                sm[OFF_E + k] = __ldg(&dec_emb[(size_t)tok * H + k]);
        }
        __syncthreads();

        // ---- S1: attn scores / C1 / hh-dots ----
        if (gw < 64) {
            const int l = gw;
            const float4* w4 = (const float4*)(W_attn + (size_t)l * 2 * H);
            const float4* e4 = (const float4*)(sm + OFF_E);
            const float4* h4 = (const float4*)(sm + OFF_H);
            float acc = 0.f;
            for (int k4 = lane; k4 < H / 4; k4 += 32) {
                float4 w = __ldg(&w4[k4]);        float4 x = e4[k4];
                acc += w.x*x.x + w.y*x.y + w.z*x.z + w.w*x.w;
            }
            for (int k4 = lane; k4 < H / 4; k4 += 32) {
                float4 w = __ldg(&w4[H / 4 + k4]); float4 x = h4[k4];
                acc += w.x*x.x + w.y*x.y + w.z*x.z + w.w*x.w;
            }
            acc = wredsum(acc);
            if (lane == 0) g_s[l] = acc + __ldg(&b_attn[l]);
        } else if (gw < 64 + H) {
            const int j = gw - 64;
            const float4* w4 = (const float4*)(W_comb + (size_t)j * 2 * H);
            const float4* e4 = (const float4*)(sm + OFF_E);
            float acc = 0.f;
            for (int k4 = lane; k4 < H / 4; k4 += 32) {
                float4 w = __ldg(&w4[k4]); float4 x = e4[k4];
                acc += w.x*x.x + w.y*x.y + w.z*x.z + w.w*x.w;
            }
            acc = wredsum(acc);
            if (lane == 0) g_c1[j] = acc + __ldg(&b_comb[j]);
        } else if (gw < 64 + 2 * H) {
            const int i = gw - 64 - H;
            const float4* w0 = (const float4*)(dec_W_hh + (size_t)i * H);
            const float4* w1 = (const float4*)(dec_W_hh + (size_t)(H + i) * H);
            const float4* w2 = (const float4*)(dec_W_hh + (size_t)(2 * H + i) * H);
            const float4* vv = (const float4*)(sm + OFF_H);
            float a0 = 0.f, a1 = 0.f, a2 = 0.f;
            for (int k4 = lane; k4 < H / 4; k4 += 32) {
                float4 x4 = vv[k4], w;
                w = __ldg(&w0[k4]); a0 += w.x*x4.x + w.y*x4.y + w.z*x4.z + w.w*x4.w;
                w = __ldg(&w1[k4]); a1 += w.x*x4.x + w.y*x4.y + w.z*x4.z + w.w*x4.w;
                w = __ldg(&w2[k4]); a2 += w.x*x4.x + w.y*x4.y + w.z*x4.z + w.w*x4.w;
            }
            a0 = wredsum(a0); a1 = wredsum(a1); a2 = wredsum(a2);
            if (lane == 0) {
                float* p = g_part + i * 8 + 3;
                p[0] = a0; p[1] = a1; p[2] = a2;
            }
        }
        gbar(gen, nblk, bid);

        // ---- S2: warp-parallel softmax; x[j] = relu(C1[j] + M[j,:].aw) ----
        if (warp == 0) {
            float v0 = __ldcg(&g_s[lane]);
            float v1 = __ldcg(&g_s[lane + 32]);
            float m = fmaxf(v0, v1);
#pragma unroll
            for (int o = 16; o; o >>= 1) m = fmaxf(m, __shfl_xor_sync(0xffffffffu, m, o));
            float e0 = expf(v0 - m), e1 = expf(v1 - m);
            float s = e0 + e1;
#pragma unroll
            for (int o = 16; o; o >>= 1) s += __shfl_xor_sync(0xffffffffu, s, o);
            float inv = 1.f / s;
            sm[OFF_AW + lane] = e0 * inv;
            sm[OFF_AW + lane + 32] = e1 * inv;
        }
        __syncthreads();
        if (bid == 0 && tid < 64) out[OUT_ATT + t * 64 + tid] = sm[OFF_AW + tid];
        if (gw < H) {
            const int j = gw;
            float a = sm[OFF_AW + lane]      * __ldcg(&g_M[j * L + lane]) +
                      sm[OFF_AW + lane + 32] * __ldcg(&g_M[j * L + lane + 32]);
            a = wredsum(a);
            if (lane == 0) g_x[j] = fmaxf(0.f, a + __ldcg(&g_c1[j]));
        }
        gbar(gen, nblk, bid);

        // ---- S3: ih-dots ----
        for (int k = tid; k < H; k += TPB) sm[OFF_X + k] = __ldcg(&g_x[k]);
        __syncthreads();
        if (gw < H) {
            const int i = gw;
            const float4* w0 = (const float4*)(dec_W_ih + (size_t)i * H);
            const float4* w1 = (const float4*)(dec_W_ih + (size_t)(H + i) * H);
            const float4* w2 = (const float4*)(dec_W_ih + (size_t)(2 * H + i) * H);
            const float4* vv = (const float4*)(sm + OFF_X);
            float a0 = 0.f, a1 = 0.f, a2 = 0.f;
            for (int k4 = lane; k4 < H / 4; k4 += 32) {
                float4 x4 = vv[k4], w;
                w = __ldg(&w0[k4]); a0 += w.x*x4.x + w.y*x4.y + w.z*x4.z + w.w*x4.w;
                w = __ldg(&w1[k4]); a1 += w.x*x4.x + w.y*x4.y + w.z*x4.z + w.w*x4.w;
                w = __ldg(&w2[k4]); a2 += w.x*x4.x + w.y*x4.y + w.z*x4.z + w.w*x4.w;
            }
            a0 = wredsum(a0); a1 = wredsum(a1); a2 = wredsum(a2);
            if (lane == 0) {
                float* p = g_part + i * 8;
                p[0] = a0; p[1] = a1; p[2] = a2;
            }
        }
        gbar(gen, nblk, bid);

        // ---- S4 prologue: gates -> h2, frozen h, ||h2|| (every block) ----
        {
            float sq = 0.f;
            for (int i = tid; i < H; i += TPB) {
                const float* p = g_part + i * 8;
                float gir = __ldcg(&p[0]) + __ldg(&dec_b_ih[i]);
                float giz = __ldcg(&p[1]) + __ldg(&dec_b_ih[H + i]);
                float gin = __ldcg(&p[2]) + __ldg(&dec_b_ih[2 * H + i]);
                float ghr = __ldcg(&p[3]) + __ldg(&dec_b_hh[i]);
                float ghz = __ldcg(&p[4]) + __ldg(&dec_b_hh[H + i]);
                float ghn = __ldcg(&p[5]) + __ldg(&dec_b_hh[2 * H + i]);
                float rg = sigm(gir + ghr);
                float zg = sigm(giz + ghz);
                float ng = tanhf(gin + rg * ghn);
                float hp = sm[OFF_H + i];
                float h2 = (1.f - zg) * ng + zg * hp;
                sm[OFF_H2 + i] = h2;
                sm[OFF_H + i]  = st_i[1] ? hp : h2;
                sq += h2 * h2;
            }
            sq = wredsum(sq);
            if (lane == 0) sm[OFF_SRED + 128 + warp] = sq;
        }
        __syncthreads();
        if (tid == 0) {
            float s = 0.f;
            for (int w = 0; w < NWARP; w++) s += sm[OFF_SRED + 128 + w];
            sm[OFF_HN] = sqrtf(s);
            ((int*)(sm + OFF_CCNT))[0] = 0;
        }
        __syncthreads();

        // ---- S4 main: bf16 logits, 2 rows per warp-iteration ----
        {
            float wsum = 0.f, wmaxv = -3.4e38f;
            const float4* hv = (const float4*)(sm + OFF_H2);
            for (int r = vr0 + (warp << 1); r < vr1; r += (NWARP << 1)) {
                const bool two = (r + 1 < vr1);
                const uint4* wb0 = (const uint4*)(g_Wbf + (size_t)r * H);
                const uint4* wb1 = (const uint4*)(g_Wbf + (size_t)(r + 1) * H);
                float acc0 = 0.f, acc1 = 0.f;
#pragma unroll
                for (int j = 0; j < 4; j++) {
                    uint4 w0v = __ldg(&wb0[j * 32 + lane]);
                    uint4 w1v = two ? __ldg(&wb1[j * 32 + lane]) : make_uint4(0u, 0u, 0u, 0u);
                    int hu = (j * 32 + lane) * 2;
                    float4 hA = hv[hu], hB = hv[hu + 1];
                    float2 f0 = bf2f(w0v.x), f1 = bf2f(w0v.y);
                    float2 f2 = bf2f(w0v.z), f3 = bf2f(w0v.w);
                    acc0 += f0.x*hA.x + f0.y*hA.y + f1.x*hA.z + f1.y*hA.w
                          + f2.x*hB.x + f2.y*hB.y + f3.x*hB.z + f3.y*hB.w;
                    float2 g0 = bf2f(w1v.x), g1 = bf2f(w1v.y);
                    float2 g2 = bf2f(w1v.z), g3 = bf2f(w1v.w);
                    acc1 += g0.x*hA.x + g0.y*hA.y + g1.x*hA.z + g1.y*hA.w
                          + g2.x*hB.x + g2.y*hB.y + g3.x*hB.z + g3.y*hB.w;
                }
                acc0 = wredsum(acc0); acc1 = wredsum(acc1);
                if (lane == 0) {
                    float l0 = acc0 + __ldg(&b_out[r]);
                    out[(size_t)t * V + r] = l0;
                    wsum += expf(l0);
                    wmaxv = fmaxf(wmaxv, l0);
                    if (two) {
                        float l1 = acc1 + __ldg(&b_out[r + 1]);
                        out[(size_t)t * V + r + 1] = l1;
                        wsum += expf(l1);
                        wmaxv = fmaxf(wmaxv, l1);
                    }
                }
            }
            __syncthreads();
            if (lane == 0) {
                sm[OFF_SRED + warp]      = wsum;
                sm[OFF_SRED + 64 + warp] = wmaxv;
            }
            __syncthreads();
            if (tid == 0) {
                float bs = 0.f, bm = -3.4e38f;
                for (int w = 0; w < NWARP; w++) {
                    bs += sm[OFF_SRED + w];
                    bm = fmaxf(bm, sm[OFF_SRED + 64 + w]);
                }
                g_sums[bid] = bs;
                sm[OFF_BMAX] = bm;
            }
            __syncthreads();

            // ---- refine: exact fp32 recompute of candidate rows ----
            {
                float Emax = EFAC * sm[OFF_BMN] * sm[OFF_HN];
                float thr = sm[OFF_BMAX] - (2.f * Emax + 1e-7f);
                int* ccnt = (int*)(sm + OFF_CCNT);
                int* cand = (int*)(sm + OFF_CAND);
                size_t base = (size_t)t * V;
                for (int r = vr0 + tid; r < vr1; r += TPB) {
                    if (out[base + r] >= thr) {
                        int idx = atomicAdd(ccnt, 1);
                        cand[idx] = r;          // nc <= RPBV(211) < 512 always
                    }
                }
                __syncthreads();
                int nc = *ccnt;
                unsigned long long wkey = 0ull;
                for (int c = warp; c < nc; c += NWARP) {
                    int r = cand[c];
                    const float4* w4 = (const float4*)(W_out + (size_t)r * H);
                    float acc = 0.f;
#pragma unroll 2
                    for (int k4 = lane; k4 < H / 4; k4 += 32) {
                        float4 w = __ldg(&w4[k4]); float4 h4 = hv[k4];
                        acc += w.x*h4.x + w.y*h4.y + w.z*h4.z + w.w*h4.w;
                    }
                    acc = wredsum(acc);
                    if (lane == 0) {
                        unsigned long long k = packkey(acc + __ldg(&b_out[r]), r);
                        if (k > wkey) wkey = k;
                    }
                }
                if (lane == 0) ((unsigned long long*)(sm + OFF_KRED))[warp] = wkey;
                __syncthreads();
                if (tid == 0) {
                    unsigned long long bk = 0ull;
                    for (int w = 0; w < NWARP; w++) {
                        unsigned long long k = ((unsigned long long*)(sm + OFF_KRED))[w];
                        if (k > bk) bk = k;
                    }
                    g_keys[bid] = bk;
                }
            }
        }
        gbar(gen, nblk, bid);
    }

    // ---- final: reduce last step; write last token; epilogue lse subtract ----
    if (warp == 0) {
        float s = 0.f; unsigned long long bk = 0ull;
        for (int b = lane; b < nblk; b += 32) {
            s += __ldcg(&g_sums[b]);
            unsigned long long k = __ldcg(&g_keys[b]);
            if (k > bk) bk = k;
        }
        s = wredsum(s);
#pragma unroll
        for (int o = 16; o; o >>= 1) {
            unsigned long long k = __shfl_down_sync(0xffffffffu, bk, o);
            if (k > bk) bk = k;
        }
        if (lane == 0) {
            int nxtTok = (int)(~(unsigned)(bk & 0xffffffffu));
            int done = st_i[1];
            st_i[0] = done ? st_i[0] : nxtTok;
            sm[OFF_LSEH + (L - 1)] = logf(s);
            if (bid == 0) out[OUT_TOK + (L - 1)] = (float)st_i[0];
        }
    }
    __syncthreads();
    for (int t = 0; t < L; t++) {
        float lse = sm[OFF_LSEH + t];
        size_t base = (size_t)t * V;
        for (int r = vr0 + tid; r < vr1; r += TPB)
            out[base + r] = out[base + r] - lse;
    }
}

// ------------------------- launch -------------------------
extern "C" void kernel_launch(void* const* d_in, const int* in_sizes, int n_in,
                              void* d_out, int out_size) {
    (void)in_sizes; (void)n_in; (void)out_size;
    int dev = 0; cudaGetDevice(&dev);
    int sms = 0; cudaDeviceGetAttribute(&sms, cudaDevAttrMultiProcessorCount, dev);
    if (sms < 1) sms = 148;
    int nblk = sms > 256 ? 256 : sms;

    size_t smemB = (size_t)SMEM_FLOATS * sizeof(float);
    cudaFuncSetAttribute(ms2s_kernel, cudaFuncAttributeMaxDynamicSharedMemorySize, (int)smemB);

    ms2s_kernel<<<nblk, TPB, smemB>>>(
        (const int*)d_in[0],   (const int*)d_in[1],
        (const float*)d_in[2], (const float*)d_in[3], (const float*)d_in[4],
        (const float*)d_in[5], (const float*)d_in[6],
        (const float*)d_in[7], (const float*)d_in[8], (const float*)d_in[9],
        (const float*)d_in[10], (const float*)d_in[11],
        (const float*)d_in[12], (const float*)d_in[13], (const float*)d_in[14],
        (const float*)d_in[15], (const float*)d_in[16], (const float*)d_in[17],
        (float*)d_out, nblk);
}

// round 17
// speedup vs baseline: 1.2611x; 1.0016x over previous
#include <cuda_runtime.h>
#include <cuda_bf16.h>
#include <cstdint>
#include <cstddef>

#define H 1024
#define V 32000
#define L 64
#define NEC 3
#define TPB 512
#define NWARP 16
#define EOS_TOK 1

#define TILE_STRIDE 1025
#define SMEM_FLOATS (32 * TILE_STRIDE + 64)

// decode-area smem offsets (in floats)
#define OFF_E    0
#define OFF_H    1024
#define OFF_X    4096
#define OFF_H2   5120
#define OFF_AW   6144
#define OFF_SRED 6208
#define OFF_KRED 6464   /* ull[128] -> 256 floats */
#define OFF_ST   6976   /* int[2]: tok, done */
#define OFF_BMAX 6981
#define OFF_HN   6982
#define OFF_BMN  6983
#define OFF_CCNT 6984   /* int */
#define OFF_CAND 6992   /* int[512] */
#define OFF_LSEH 7600   /* float[64] lse history */

#define EFAC 0.004f

#define OUT_ATT  (L * V)
#define OUT_TOK  (L * V + L * L)

// ------------------------- device scratch (static; no allocs) -------------------------
__device__ float g_gi[(size_t)NEC * 3 * H * L];   // [e][row][t]
__device__ float g_hist[(size_t)NEC * L * H];
__device__ float g_eo[L * H];
__device__ float g_M[H * L];                      // [j][l]
__device__ float g_epart[NEC * 3 * H];            // encoder gate-dot partials
__device__ float g_part[H * 8];                   // decode: [i]: 0..2 ih, 3..5 hh
__device__ float g_s2[128];                       // attn score half-dots
__device__ float g_c1[H];
__device__ float g_x[H];
__device__ float g_wn[V];                         // row norms of W_out
__device__ __nv_bfloat16 g_Wbf[(size_t)V * H];    // bf16 copy of W_out
__device__ unsigned long long g_keys[256];
__device__ float g_sums[256];

// tree barrier state — FENCE-FREE protocol (no __threadfence -> no L1D flush)
__device__ unsigned g_arrL[8 * 64];
__device__ unsigned g_arrM = 0;
__device__ unsigned g_release = 0;
__device__ unsigned g_garr[3 * 64];
__device__ unsigned g_grel[3 * 64];

// ------------------------- helpers -------------------------
__device__ __forceinline__ unsigned ldacq(const unsigned* p) {
    unsigned v;
    asm volatile("ld.acquire.gpu.global.u32 %0, [%1];" : "=r"(v) : "l"(p) : "memory");
    return v;
}
__device__ __forceinline__ void strel(unsigned* p, unsigned v) {
    asm volatile("st.release.gpu.global.u32 [%0], %1;" :: "l"(p), "r"(v) : "memory");
}
__device__ __forceinline__ void strelax(unsigned* p, unsigned v) {
    asm volatile("st.relaxed.gpu.global.u32 [%0], %1;" :: "l"(p), "r"(v) : "memory");
}
__device__ __forceinline__ unsigned atom_add_acqrel(unsigned* p, unsigned v) {
    unsigned r;
    asm volatile("atom.acq_rel.gpu.global.add.u32 %0, [%1], %2;"
                 : "=r"(r) : "l"(p), "r"(v) : "memory");
    return r;
}

__device__ __forceinline__ float wredsum(float v) {
#pragma unroll
    for (int o = 16; o; o >>= 1) v += __shfl_down_sync(0xffffffffu, v, o);
    return v;
}

__device__ __forceinline__ unsigned long long packkey(float v, int r) {
    unsigned u = __float_as_uint(v);
    u = (u & 0x80000000u) ? ~u : (u | 0x80000000u);
    return ((unsigned long long)u << 32) | (unsigned)(~(unsigned)r);
}

__device__ __forceinline__ float sigm(float x) { return 1.f / (1.f + expf(-x)); }

__device__ __forceinline__ float2 bf2f(unsigned u) {
    __nv_bfloat162 t = *reinterpret_cast<__nv_bfloat162*>(&u);
    return __bfloat1622float2(t);
}

// warp dot of len-1024: weight ptr (global), vec ptr (smem)
__device__ __forceinline__ float dot1024(const float* w, const float* v, int lane) {
    const float4* w4 = (const float4*)w;
    const float4* v4 = (const float4*)v;
    float acc = 0.f;
#pragma unroll
    for (int k4 = lane; k4 < H / 4; k4 += 32) {
        float4 a = __ldg(&w4[k4]);
        float4 b = v4[k4];
        acc += a.x*b.x + a.y*b.y + a.z*b.z + a.w*b.w;
    }
    return wredsum(acc);
}

// two-level grid barrier (8 leaves), fence-free; all CTAs resident (1 CTA/SM)
__device__ __forceinline__ void gbar(unsigned& gen, int nb, int bid) {
    __syncthreads();
    if (threadIdx.x == 0) {
        const int leaf = bid & 7;
        const unsigned lcnt = (unsigned)((nb - leaf + 7) >> 3);
        unsigned t = atom_add_acqrel(&g_arrL[leaf * 64], 1u);
        if (t == lcnt - 1u) {
            strelax(&g_arrL[leaf * 64], 0u);
            unsigned m = atom_add_acqrel(&g_arrM, 1u);
            if (m == 7u) {
                strelax(&g_arrM, 0u);
                strel(&g_release, gen + 1u);
            } else {
                while (ldacq(&g_release) == gen) { }
            }
        } else {
            while (ldacq(&g_release) == gen) { }
        }
    }
    gen++;
    __syncthreads();
}

// group barrier for one encoder's block set (fence-free)
__device__ __forceinline__ void gbar_grp(unsigned& gen, int e, unsigned cnt) {
    __syncthreads();
    if (threadIdx.x == 0) {
        unsigned t = atom_add_acqrel(&g_garr[e * 64], 1u);
        if (t == cnt - 1u) {
            strelax(&g_garr[e * 64], 0u);
            strel(&g_grel[e * 64], gen + 1u);
        } else {
            while (ldacq(&g_grel[e * 64]) == gen) { }
        }
    }
    gen++;
    __syncthreads();
}

// ------------------------- kernel -------------------------
__global__ void __launch_bounds__(TPB, 1)
ms2s_kernel(const int* __restrict__ q_ids,
            const int* __restrict__ cand_ids,
            const float* __restrict__ enc_emb,
            const float* __restrict__ enc_W_ih,
            const float* __restrict__ enc_W_hh,
            const float* __restrict__ enc_b_ih,
            const float* __restrict__ enc_b_hh,
            const float* __restrict__ dec_emb,
            const float* __restrict__ W_attn,
            const float* __restrict__ b_attn,
            const float* __restrict__ W_comb,
            const float* __restrict__ b_comb,
            const float* __restrict__ dec_W_ih,
            const float* __restrict__ dec_W_hh,
            const float* __restrict__ dec_b_ih,
            const float* __restrict__ dec_b_hh,
            const float* __restrict__ W_out,
            const float* __restrict__ b_out,
            float* __restrict__ out,
            int nblk)
{
    extern __shared__ float sm[];
    const int tid  = threadIdx.x;
    const int warp = tid >> 5;
    const int lane = tid & 31;
    const int bid  = blockIdx.x;
    const int gw   = bid * NWARP + warp;
    const int TW   = nblk * NWARP;
    int* st_i = (int*)(sm + OFF_ST);

    unsigned gen = ldacq(&g_release);

    // =====================================================================
    // Setup: fused bf16-convert + row-norm of W_out; zero partials; gi
    // =====================================================================
    const int RPBV = (V + nblk - 1) / nblk;
    const int vr0 = bid * RPBV, vr1 = min(V, vr0 + RPBV);

    for (int r = vr0 + warp; r < vr1; r += NWARP) {
        const float4* src = (const float4*)(W_out + (size_t)r * H);
        uint2* dst = (uint2*)(g_Wbf + (size_t)r * H);
        float ss = 0.f;
#pragma unroll
        for (int k4 = lane; k4 < 256; k4 += 32) {
            float4 a = __ldg(&src[k4]);
            ss += a.x*a.x + a.y*a.y + a.z*a.z + a.w*a.w;
            unsigned short s0 = __bfloat16_as_ushort(__float2bfloat16_rn(a.x));
            unsigned short s1 = __bfloat16_as_ushort(__float2bfloat16_rn(a.y));
            unsigned short s2 = __bfloat16_as_ushort(__float2bfloat16_rn(a.z));
            unsigned short s3 = __bfloat16_as_ushort(__float2bfloat16_rn(a.w));
            uint2 o;
            o.x = (unsigned)s0 | ((unsigned)s1 << 16);
            o.y = (unsigned)s2 | ((unsigned)s3 << 16);
            dst[k4] = o;
        }
        ss = wredsum(ss);
        if (lane == 0) g_wn[r] = sqrtf(ss);
    }
    for (int i = bid * TPB + tid; i < NEC * 3 * H; i += nblk * TPB) g_epart[i] = 0.f;

    {
        const int be   = bid % 3;
        const int rank = bid / 3;
        const int cnt  = (nblk - be + 2) / 3;
        const int rpb  = (3 * H + cnt - 1) / cnt;
        const int r0   = rank * rpb;
        const int r1   = min(3 * H, r0 + rpb);
        int* ids_s = (int*)(sm + 32 * TILE_STRIDE);
        const float* Wih = enc_W_ih + (size_t)be * 3 * H * H;
        const float* emb = enc_emb + (size_t)be * V * H;

        for (int p = 0; p < 2; p++) {
            __syncthreads();
            if (tid < 32) {
                int tIdx = p * 32 + tid;
                ids_s[tid] = (be == 0) ? q_ids[tIdx] : cand_ids[(be - 1) * L + tIdx];
            }
            __syncthreads();
            for (int idx = tid; idx < 32 * H; idx += TPB) {
                int tt = idx >> 10, k = idx & (H - 1);
                sm[tt * TILE_STRIDE + k] = __ldg(&emb[(size_t)ids_s[tt] * H + k]);
            }
            __syncthreads();
            for (int r = r0 + warp; r < r1; r += NWARP) {
                const float4* w4 = (const float4*)(Wih + (size_t)r * H);
                const float* xs = sm + lane * TILE_STRIDE;
                float acc = 0.f;
#pragma unroll 4
                for (int k4 = 0; k4 < H / 4; k4++) {
                    float4 w = __ldg(&w4[k4]);
                    int k = k4 * 4;
                    acc += w.x * xs[k] + w.y * xs[k + 1] + w.z * xs[k + 2] + w.w * xs[k + 3];
                }
                g_gi[((size_t)be * 3 * H + r) * L + p * 32 + lane] =
                    acc + __ldg(&enc_b_ih[be * 3 * H + r]);
            }
        }
    }
    gbar(gen, nblk, bid);

    // =====================================================================
    // Encoder recurrence: single-dot units + redundant gate prologue
    // =====================================================================
    {
        const int e    = bid % 3;
        const int rank = bid / 3;
        const unsigned cnt = (unsigned)((nblk - e + 2) / 3);
        const int TWg  = (int)cnt * NWARP;
        const int gwg  = rank * NWARP + warp;
        unsigned genG = ldacq(&g_grel[e * 64]);
        const float* Whh = enc_W_hh + (size_t)e * 3 * H * H;
        const float* bhh = enc_b_hh + e * 3 * H;
        const float* ep  = g_epart + e * 3 * H;

        for (int k = tid; k < H; k += TPB) sm[OFF_H + k] = 0.f;   // h_0 = 0
        __syncthreads();

        for (int t = 0; t < L; t++) {
            if (t > 0) {
                for (int i = tid; i < H; i += TPB) {
                    float ar = __ldcg(&ep[i]);
                    float az = __ldcg(&ep[H + i]);
                    float an = __ldcg(&ep[2 * H + i]);
                    const size_t gbase = ((size_t)e * 3 * H + i) * L + (t - 1);
                    float gir = __ldcg(&g_gi[gbase]);
                    float giz = __ldcg(&g_gi[gbase + (size_t)H * L]);
                    float gin = __ldcg(&g_gi[gbase + (size_t)2 * H * L]);
                    float ghr = ar + __ldg(&bhh[i]);
                    float ghz = az + __ldg(&bhh[H + i]);
                    float ghn = an + __ldg(&bhh[2 * H + i]);
                    float rg = sigm(gir + ghr);
                    float zg = sigm(giz + ghz);
                    float ng = tanhf(gin + rg * ghn);
                    float hp = sm[OFF_H + i];
                    float hn2 = (1.f - zg) * ng + zg * hp;
                    sm[OFF_H + i] = hn2;
                    if (rank == 0) g_hist[((size_t)e * L + (t - 1)) * H + i] = hn2;
                }
                __syncthreads();
            }
            for (int u = gwg; u < 3 * H; u += TWg) {
                float acc = dot1024(Whh + (size_t)u * H, sm + OFF_H, lane);
                if (lane == 0) g_epart[e * 3 * H + u] = acc;
            }
            gbar_grp(genG, e, cnt);
        }
        // epilogue: hist[L-1]
        for (int i = tid; i < H; i += TPB) {
            float ar = __ldcg(&ep[i]);
            float az = __ldcg(&ep[H + i]);
            float an = __ldcg(&ep[2 * H + i]);
            const size_t gbase = ((size_t)e * 3 * H + i) * L + (L - 1);
            float gir = __ldcg(&g_gi[gbase]);
            float giz = __ldcg(&g_gi[gbase + (size_t)H * L]);
            float gin = __ldcg(&g_gi[gbase + (size_t)2 * H * L]);
            float ghr = ar + __ldg(&bhh[i]);
            float ghz = az + __ldg(&bhh[H + i]);
            float ghn = an + __ldg(&bhh[2 * H + i]);
            float rg = sigm(gir + ghr);
            float zg = sigm(giz + ghz);
            float ng = tanhf(gin + rg * ghn);
            float hp = sm[OFF_H + i];
            float hn2 = (1.f - zg) * ng + zg * hp;
            if (rank == 0) g_hist[((size_t)e * L + (L - 1)) * H + i] = hn2;
        }
    }
    gbar(gen, nblk, bid);

    // ============== enc_outs = hist0 + (hist1 + hist2)/2 ==============
    for (int i = bid * TPB + tid; i < L * H; i += nblk * TPB)
        g_eo[i] = __ldcg(&g_hist[i]) +
                  0.5f * (__ldcg(&g_hist[L * H + i]) + __ldcg(&g_hist[2 * L * H + i]));
    gbar(gen, nblk, bid);

    // ============== M[j][l] = W_comb[j, H:2H] . enc_outs[l] ==============
    {
        const int mrpb = (H + nblk - 1) / nblk;
        const int j0 = bid * mrpb, j1 = min(H, j0 + mrpb);
        for (int p = 0; p < 2; p++) {
            __syncthreads();
            for (int idx = tid; idx < 32 * H; idx += TPB) {
                int tt = idx >> 10, k = idx & (H - 1);
                sm[tt * TILE_STRIDE + k] = __ldcg(&g_eo[(size_t)(p * 32 + tt) * H + k]);
            }
            __syncthreads();
            for (int j = j0 + warp; j < j1; j += NWARP) {
                const float4* w4 = (const float4*)(W_comb + (size_t)j * 2 * H + H);
                const float* xs = sm + lane * TILE_STRIDE;
                float acc = 0.f;
#pragma unroll 4
                for (int k4 = 0; k4 < H / 4; k4++) {
                    float4 w = __ldg(&w4[k4]);
                    int k = k4 * 4;
                    acc += w.x * xs[k] + w.y * xs[k + 1] + w.z * xs[k + 2] + w.w * xs[k + 3];
                }
                g_M[j * L + p * 32 + lane] = acc;
            }
        }
    }
    gbar(gen, nblk, bid);

    // =====================================================================
    // Greedy attention decode: 64 steps x 4 barriers, balanced single-dot S1/S3
    // =====================================================================
    for (int k = tid; k < H; k += TPB) sm[OFF_H + k] = 0.f;
    {
        float mn = 0.f;
        for (int r = vr0 + tid; r < vr1; r += TPB) mn = fmaxf(mn, __ldcg(&g_wn[r]));
#pragma unroll
        for (int o = 16; o; o >>= 1) mn = fmaxf(mn, __shfl_xor_sync(0xffffffffu, mn, o));
        if (lane == 0) sm[OFF_SRED + 128 + warp] = mn;
        __syncthreads();
        if (tid == 0) {
            float m = 0.f;
            for (int w = 0; w < NWARP; w++) m = fmaxf(m, sm[OFF_SRED + 128 + w]);
            sm[OFF_BMN] = m;
        }
    }
    __syncthreads();

    for (int t = 0; t < L; t++) {
        // ---- pre: warp0 reduces prev step's exact argmax + approx sumexp ----
        if (t == 0) {
            if (tid == 0) { st_i[0] = 0; st_i[1] = 0; }
        } else if (warp == 0) {
            float s = 0.f; unsigned long long bk = 0ull;
            for (int b = lane; b < nblk; b += 32) {
                s += __ldcg(&g_sums[b]);
                unsigned long long k = __ldcg(&g_keys[b]);
                if (k > bk) bk = k;
            }
            s = wredsum(s);
#pragma unroll
            for (int o = 16; o; o >>= 1) {
                unsigned long long k = __shfl_down_sync(0xffffffffu, bk, o);
                if (k > bk) bk = k;
            }
            if (lane == 0) {
                int nxtTok = (int)(~(unsigned)(bk & 0xffffffffu));
                int done = st_i[1];
                st_i[0] = done ? st_i[0] : nxtTok;
                st_i[1] = done | (nxtTok == EOS_TOK);
                sm[OFF_LSEH + (t - 1)] = logf(s);
                if (bid == 0) out[OUT_TOK + (t - 1)] = (float)st_i[0];
            }
        }
        __syncthreads();
        // stage e
        {
            int tok = st_i[0];
            for (int k = tid; k < H; k += TPB)
                sm[OFF_E + k] = __ldg(&dec_emb[(size_t)tok * H + k]);
        }
        __syncthreads();

        // ---- S1: 4224 single-dot units (128 attn halves, 1024 C1, 3072 hh) ----
        for (int u = gw; u < 128 + H + 3 * H; u += TW) {
            if (u < 128) {
                const int l = u >> 1, hf = u & 1;
                float acc = dot1024(W_attn + (size_t)l * 2 * H + hf * H,
                                    sm + (hf ? OFF_H : OFF_E), lane);
                if (lane == 0) g_s2[u] = acc;
            } else if (u < 128 + H) {
                const int j = u - 128;
                float acc = dot1024(W_comb + (size_t)j * 2 * H, sm + OFF_E, lane);
                if (lane == 0) g_c1[j] = acc + __ldg(&b_comb[j]);
            } else {
                const int v2 = u - 128 - H;
                const int i = v2 & (H - 1), gate = v2 >> 10;
                float acc = dot1024(dec_W_hh + (size_t)(gate * H + i) * H,
                                    sm + OFF_H, lane);
                if (lane == 0) g_part[i * 8 + 3 + gate] = acc;
            }
        }
        gbar(gen, nblk, bid);

        // ---- S2: softmax (combine s halves); x[j] = relu(C1[j] + M[j,:].aw) ----
        if (warp == 0) {
            float v0 = __ldcg(&g_s2[2 * lane]) + __ldcg(&g_s2[2 * lane + 1]) +
                       __ldg(&b_attn[lane]);
            float v1 = __ldcg(&g_s2[2 * (lane + 32)]) + __ldcg(&g_s2[2 * (lane + 32) + 1]) +
                       __ldg(&b_attn[lane + 32]);
            float m = fmaxf(v0, v1);
#pragma unroll
            for (int o = 16; o; o >>= 1) m = fmaxf(m, __shfl_xor_sync(0xffffffffu, m, o));
            float e0 = expf(v0 - m), e1 = expf(v1 - m);
            float s = e0 + e1;
#pragma unroll
            for (int o = 16; o; o >>= 1) s += __shfl_xor_sync(0xffffffffu, s, o);
            float inv = 1.f / s;
            sm[OFF_AW + lane] = e0 * inv;
            sm[OFF_AW + lane + 32] = e1 * inv;
        }
        __syncthreads();
        if (bid == 0 && tid < 64) out[OUT_ATT + t * 64 + tid] = sm[OFF_AW + tid];
        if (gw < H) {
            const int j = gw;
            float a = sm[OFF_AW + lane]      * __ldcg(&g_M[j * L + lane]) +
                      sm[OFF_AW + lane + 32] * __ldcg(&g_M[j * L + lane + 32]);
            a = wredsum(a);
            if (lane == 0) g_x[j] = fmaxf(0.f, a + __ldcg(&g_c1[j]));
        }
        gbar(gen, nblk, bid);

        // ---- S3: 3072 single-dot ih units ----
        for (int k = tid; k < H; k += TPB) sm[OFF_X + k] = __ldcg(&g_x[k]);
        __syncthreads();
        for (int u = gw; u < 3 * H; u += TW) {
            const int i = u & (H - 1), gate = u >> 10;
            float acc = dot1024(dec_W_ih + (size_t)(gate * H + i) * H,
                                sm + OFF_X, lane);
            if (lane == 0) g_part[i * 8 + gate] = acc;
        }
        gbar(gen, nblk, bid);

        // ---- S4 prologue: gates -> h2, frozen h, ||h2|| (every block) ----
        {
            float sq = 0.f;
            for (int i = tid; i < H; i += TPB) {
                const float* p = g_part + i * 8;
                float gir = __ldcg(&p[0]) + __ldg(&dec_b_ih[i]);
                float giz = __ldcg(&p[1]) + __ldg(&dec_b_ih[H + i]);
                float gin = __ldcg(&p[2]) + __ldg(&dec_b_ih[2 * H + i]);
                float ghr = __ldcg(&p[3]) + __ldg(&dec_b_hh[i]);
                float ghz = __ldcg(&p[4]) + __ldg(&dec_b_hh[H + i]);
                float ghn = __ldcg(&p[5]) + __ldg(&dec_b_hh[2 * H + i]);
                float rg = sigm(gir + ghr);
                float zg = sigm(giz + ghz);
                float ng = tanhf(gin + rg * ghn);
                float hp = sm[OFF_H + i];
                float h2 = (1.f - zg) * ng + zg * hp;
                sm[OFF_H2 + i] = h2;
                sm[OFF_H + i]  = st_i[1] ? hp : h2;
                sq += h2 * h2;
            }
            sq = wredsum(sq);
            if (lane == 0) sm[OFF_SRED + 128 + warp] = sq;
        }
        __syncthreads();
        if (tid == 0) {
            float s = 0.f;
            for (int w = 0; w < NWARP; w++) s += sm[OFF_SRED + 128 + w];
            sm[OFF_HN] = sqrtf(s);
            ((int*)(sm + OFF_CCNT))[0] = 0;
        }
        __syncthreads();

        // ---- S4 main: bf16 logits, 2 rows per warp-iteration ----
        {
            float wsum = 0.f, wmaxv = -3.4e38f;
            const float4* hv = (const float4*)(sm + OFF_H2);
            for (int r = vr0 + (warp << 1); r < vr1; r += (NWARP << 1)) {
                const bool two = (r + 1 < vr1);
                const uint4* wb0 = (const uint4*)(g_Wbf + (size_t)r * H);
                const uint4* wb1 = (const uint4*)(g_Wbf + (size_t)(r + 1) * H);
                float acc0 = 0.f, acc1 = 0.f;
#pragma unroll
                for (int j = 0; j < 4; j++) {
                    uint4 w0v = __ldg(&wb0[j * 32 + lane]);
                    uint4 w1v = two ? __ldg(&wb1[j * 32 + lane]) : make_uint4(0u, 0u, 0u, 0u);
                    int hu = (j * 32 + lane) * 2;
                    float4 hA = hv[hu], hB = hv[hu + 1];
                    float2 f0 = bf2f(w0v.x), f1 = bf2f(w0v.y);
                    float2 f2 = bf2f(w0v.z), f3 = bf2f(w0v.w);
                    acc0 += f0.x*hA.x + f0.y*hA.y + f1.x*hA.z + f1.y*hA.w
                          + f2.x*hB.x + f2.y*hB.y + f3.x*hB.z + f3.y*hB.w;
                    float2 g0 = bf2f(w1v.x), g1 = bf2f(w1v.y);
                    float2 g2 = bf2f(w1v.z), g3 = bf2f(w1v.w);
                    acc1 += g0.x*hA.x + g0.y*hA.y + g1.x*hA.z + g1.y*hA.w
                          + g2.x*hB.x + g2.y*hB.y + g3.x*hB.z + g3.y*hB.w;
                }
                acc0 = wredsum(acc0); acc1 = wredsum(acc1);
                if (lane == 0) {
                    float l0 = acc0 + __ldg(&b_out[r]);
                    out[(size_t)t * V + r] = l0;
                    wsum += expf(l0);
                    wmaxv = fmaxf(wmaxv, l0);
                    if (two) {
                        float l1 = acc1 + __ldg(&b_out[r + 1]);
                        out[(size_t)t * V + r + 1] = l1;
                        wsum += expf(l1);
                        wmaxv = fmaxf(wmaxv, l1);
                    }
                }
            }
            __syncthreads();
            if (lane == 0) {
                sm[OFF_SRED + warp]      = wsum;
                sm[OFF_SRED + 64 + warp] = wmaxv;
            }
            __syncthreads();
            if (tid == 0) {
                float bs = 0.f, bm = -3.4e38f;
                for (int w = 0; w < NWARP; w++) {
                    bs += sm[OFF_SRED + w];
                    bm = fmaxf(bm, sm[OFF_SRED + 64 + w]);
                }
                g_sums[bid] = bs;
                sm[OFF_BMAX] = bm;
            }
            __syncthreads();

            // ---- refine: exact fp32 recompute of candidate rows ----
            {
                float Emax = EFAC * sm[OFF_BMN] * sm[OFF_HN];
                float thr = sm[OFF_BMAX] - (2.f * Emax + 1e-7f);
                int* ccnt = (int*)(sm + OFF_CCNT);
                int* cand = (int*)(sm + OFF_CAND);
                size_t base = (size_t)t * V;
                for (int r = vr0 + tid; r < vr1; r += TPB) {
                    if (out[base + r] >= thr) {
                        int idx = atomicAdd(ccnt, 1);
                        cand[idx] = r;          // nc <= RPBV(211) < 512 always
                    }
                }
                __syncthreads();
                int nc = *ccnt;
                unsigned long long wkey = 0ull;
                for (int c = warp; c < nc; c += NWARP) {
                    int r = cand[c];
                    const float4* w4 = (const float4*)(W_out + (size_t)r * H);
                    float acc = 0.f;
#pragma unroll 2
                    for (int k4 = lane; k4 < H / 4; k4 += 32) {
                        float4 w = __ldg(&w4[k4]); float4 h4 = hv[k4];
                        acc += w.x*h4.x + w.y*h4.y + w.z*h4.z + w.w*h4.w;
                    }
                    acc = wredsum(acc);
                    if (lane == 0) {
                        unsigned long long k = packkey(acc + __ldg(&b_out[r]), r);
                        if (k > wkey) wkey = k;
                    }
                }
                if (lane == 0) ((unsigned long long*)(sm + OFF_KRED))[warp] = wkey;
                __syncthreads();
                if (tid == 0) {
                    unsigned long long bk = 0ull;
                    for (int w = 0; w < NWARP; w++) {
                        unsigned long long k = ((unsigned long long*)(sm + OFF_KRED))[w];
                        if (k > bk) bk = k;
                    }
                    g_keys[bid] = bk;
                }
            }
        }
        gbar(gen, nblk, bid);
    }

    // ---- final: reduce last step; write last token; epilogue lse subtract ----
    if (warp == 0) {
        float s = 0.f; unsigned long long bk = 0ull;
        for (int b = lane; b < nblk; b += 32) {
            s += __ldcg(&g_sums[b]);
            unsigned long long k = __ldcg(&g_keys[b]);
            if (k > bk) bk = k;
        }
        s = wredsum(s);
#pragma unroll
        for (int o = 16; o; o >>= 1) {
            unsigned long long k = __shfl_down_sync(0xffffffffu, bk, o);
            if (k > bk) bk = k;
        }
        if (lane == 0) {
            int nxtTok = (int)(~(unsigned)(bk & 0xffffffffu));
            int done = st_i[1];
            st_i[0] = done ? st_i[0] : nxtTok;
            sm[OFF_LSEH + (L - 1)] = logf(s);
            if (bid == 0) out[OUT_TOK + (L - 1)] = (float)st_i[0];
        }
    }
    __syncthreads();
    for (int t = 0; t < L; t++) {
        float lse = sm[OFF_LSEH + t];
        size_t base = (size_t)t * V;
        for (int r = vr0 + tid; r < vr1; r += TPB)
            out[base + r] = out[base + r] - lse;
    }
}

// ------------------------- launch -------------------------
extern "C" void kernel_launch(void* const* d_in, const int* in_sizes, int n_in,
                              void* d_out, int out_size) {
    (void)in_sizes; (void)n_in; (void)out_size;
    int dev = 0; cudaGetDevice(&dev);
    int sms = 0; cudaDeviceGetAttribute(&sms, cudaDevAttrMultiProcessorCount, dev);
    if (sms < 1) sms = 148;
    int nblk = sms > 256 ? 256 : sms;

    size_t smemB = (size_t)SMEM_FLOATS * sizeof(float);
    cudaFuncSetAttribute(ms2s_kernel, cudaFuncAttributeMaxDynamicSharedMemorySize, (int)smemB);

    ms2s_kernel<<<nblk, TPB, smemB>>>(
        (const int*)d_in[0],   (const int*)d_in[1],
        (const float*)d_in[2], (const float*)d_in[3], (const float*)d_in[4],
        (const float*)d_in[5], (const float*)d_in[6],
        (const float*)d_in[7], (const float*)d_in[8], (const float*)d_in[9],
        (const float*)d_in[10], (const float*)d_in[11],
        (const float*)d_in[12], (const float*)d_in[13], (const float*)d_in[14],
        (const float*)d_in[15], (const float*)d_in[16], (const float*)d_in[17],
        (float*)d_out, nblk);
}